// round 17
// baseline (speedup 1.0000x reference)
#include <cuda_runtime.h>
#include <cstdint>

#define DM 1024
#define NH 16
#define DH 64
#define BB 2
#define SS 2048
#define MT (BB*SS)

// Scratch (device globals; no allocation allowed anywhere)
__device__ float g_qh[MT*DM];    // [B,H,S,DH]
__device__ float g_kh[MT*DM];    // [B,H,S,DH]
__device__ float g_vt[MT*DM];    // [B,H,DH,S]  (V transposed)
__device__ float g_at[MT*DM];    // merged-head attention output [B,S,DM]
__device__ float g_wT[4*DM*DM];  // W^T for wq,wk,wv,wo

// ---------------------------------------------------------------------------
__device__ __forceinline__ unsigned tf32r(float x) {
    unsigned u;
    asm("cvt.rna.tf32.f32 %0, %1;" : "=r"(u) : "f"(x));
    return u;
}
__device__ __forceinline__ uint4 cvt4(float4 v) {
    return make_uint4(tf32r(v.x), tf32r(v.y), tf32r(v.z), tf32r(v.w));
}
__device__ __forceinline__ void mma_tf32(float c[4], const unsigned a[4],
                                         const unsigned b[2]) {
    asm volatile(
        "mma.sync.aligned.m16n8k8.row.col.f32.tf32.tf32.f32 "
        "{%0,%1,%2,%3}, {%4,%5,%6,%7}, {%8,%9}, {%0,%1,%2,%3};"
        : "+f"(c[0]), "+f"(c[1]), "+f"(c[2]), "+f"(c[3])
        : "r"(a[0]), "r"(a[1]), "r"(a[2]), "r"(a[3]), "r"(b[0]), "r"(b[1]));
}

#define CP_A16(dst, src) \
    asm volatile("cp.async.cg.shared.global [%0], [%1], 16;" :: "r"(dst), "l"(src))
#define CP_COMMIT() asm volatile("cp.async.commit_group;" ::: "memory")
#define CP_WAIT1()  asm volatile("cp.async.wait_group 1;" ::: "memory")
#define CP_WAIT0()  asm volatile("cp.async.wait_group 0;" ::: "memory")

struct GA { const float* A; const float* W; const float* bias; float* out; int mode; };
struct G3 { GA g[3]; };

// ---------------------------------------------------------------------------
// Fused weight transposes: wt[z][n*DM + k] = w_z[k*DM + n]
// ---------------------------------------------------------------------------
__global__ __launch_bounds__(256) void transp4(const float* __restrict__ w0,
                                               const float* __restrict__ w1,
                                               const float* __restrict__ w2,
                                               const float* __restrict__ w3,
                                               float* __restrict__ wt)
{
    __shared__ float tl[32][33];
    const float* w = (blockIdx.z == 0) ? w0 : (blockIdx.z == 1) ? w1
                    : (blockIdx.z == 2) ? w2 : w3;
    float* dst = wt + (size_t)blockIdx.z * DM * DM;
    int x = blockIdx.x * 32 + threadIdx.x;
    int y = blockIdx.y * 32 + threadIdx.y;
    #pragma unroll
    for (int j = 0; j < 32; j += 8)
        tl[threadIdx.y + j][threadIdx.x] = w[(size_t)(y + j) * DM + x];
    __syncthreads();
    int x2 = blockIdx.y * 32 + threadIdx.x;
    int y2 = blockIdx.x * 32 + threadIdx.y;
    #pragma unroll
    for (int j = 0; j < 32; j += 8)
        dst[(size_t)(y2 + j) * DM + x2] = tl[threadIdx.x][threadIdx.y + j];
}

// ---------------------------------------------------------------------------
// TF32 GEMM, double-buffered, conflict-free padded row-major smem.
// Block 128x128, BK=16, 256 threads (8 warps, warp tile 32x64), 2 CTAs/SM
// -> 16 warps/SM for latency cover.
// ---------------------------------------------------------------------------
__global__ __launch_bounds__(256, 2) void gemm_tf32(G3 P)
{
    __shared__ __align__(16) unsigned As[2][2560];   // [buf][row128][20]
    __shared__ __align__(16) unsigned Bs[2][2560];   // [buf][nrow128][20]

    const GA ga = P.g[blockIdx.z];
    const int tid = threadIdx.x, lane = tid & 31, wid = tid >> 5;
    const int g = lane >> 2, t = lane & 3;
    const int bm = blockIdx.y * 128, bn = blockIdx.x * 128;

    // Staging: one row per thread-pair: row = tid>>1, half = (tid&1)*8
    const int sr = tid >> 1, skq = (tid & 1) << 3;
    const float* Aptr = ga.A + (size_t)(bm + sr) * DM + skq;
    const float* Bptr = ga.W + (size_t)(bn + sr) * DM + skq;
    const unsigned stBase = sr * 20 + skq;

    const int wm = (wid >> 1) * 32, wn = (wid & 1) * 64;
    const unsigned aB = (wm + g) * 20 + t;
    const unsigned bB = (wn + g) * 20 + t;

    float acc[2][8][4];
    #pragma unroll
    for (int im = 0; im < 2; im++)
        #pragma unroll
        for (int jn = 0; jn < 8; jn++)
            #pragma unroll
            for (int r = 0; r < 4; r++) acc[im][jn][r] = 0.f;

    float4 ra0, ra1, rb0, rb1;

#define G_LOAD(K0) do {                                                     \
    ra0 = *(const float4*)(Aptr + (K0));                                    \
    ra1 = *(const float4*)(Aptr + (K0) + 4);                                \
    rb0 = *(const float4*)(Bptr + (K0));                                    \
    rb1 = *(const float4*)(Bptr + (K0) + 4);                                \
} while (0)

#define G_STORE(BUF) do {                                                   \
    *(uint4*)&As[BUF][stBase]     = cvt4(ra0);                              \
    *(uint4*)&As[BUF][stBase + 4] = cvt4(ra1);                              \
    *(uint4*)&Bs[BUF][stBase]     = cvt4(rb0);                              \
    *(uint4*)&Bs[BUF][stBase + 4] = cvt4(rb1);                              \
} while (0)

    G_LOAD(0);
    G_STORE(0);
    __syncthreads();

    for (int kc = 0; kc < 64; kc++) {
        if (kc < 63) G_LOAD((kc + 1) * 16);
        const int buf = kc & 1;
        #pragma unroll
        for (int kt = 0; kt < 2; kt++) {
            unsigned a[2][4], b[8][2];
            #pragma unroll
            for (int im = 0; im < 2; im++) {
                unsigned base = aB + im * 320 + kt * 8;
                a[im][0] = As[buf][base];
                a[im][1] = As[buf][base + 160];
                a[im][2] = As[buf][base + 4];
                a[im][3] = As[buf][base + 164];
            }
            #pragma unroll
            for (int jn = 0; jn < 8; jn++) {
                unsigned base = bB + jn * 160 + kt * 8;
                b[jn][0] = Bs[buf][base];
                b[jn][1] = Bs[buf][base + 4];
            }
            #pragma unroll
            for (int im = 0; im < 2; im++)
                #pragma unroll
                for (int jn = 0; jn < 8; jn++)
                    mma_tf32(acc[im][jn], a[im], b[jn]);
        }
        if (kc < 63) G_STORE((kc + 1) & 1);
        __syncthreads();
    }

    #pragma unroll
    for (int im = 0; im < 2; im++) {
        int r0 = bm + wm + im * 16 + g;
        int r1 = r0 + 8;
        #pragma unroll
        for (int jn = 0; jn < 8; jn++) {
            int col = bn + wn + jn * 8 + t * 2;
            float b0 = ga.bias[col], b1 = ga.bias[col + 1];
            float v00 = acc[im][jn][0] + b0, v01 = acc[im][jn][1] + b1;
            float v10 = acc[im][jn][2] + b0, v11 = acc[im][jn][3] + b1;
            if (ga.mode == 0) {
                float* p0 = ga.out + (size_t)r0 * DM + col;
                float* p1 = ga.out + (size_t)r1 * DM + col;
                p0[0] = v00; p0[1] = v01;
                p1[0] = v10; p1[1] = v11;
            } else {
                int h = col >> 6, d = col & 63;
                int b_0 = r0 >> 11, s_0 = r0 & (SS - 1);
                int b_1 = r1 >> 11, s_1 = r1 & (SS - 1);
                if (ga.mode == 1) {
                    float* p0 = ga.out + (((size_t)(b_0 * NH + h)) * SS + s_0) * DH + d;
                    float* p1 = ga.out + (((size_t)(b_1 * NH + h)) * SS + s_1) * DH + d;
                    p0[0] = v00; p0[1] = v01;
                    p1[0] = v10; p1[1] = v11;
                } else {
                    float* base0 = ga.out + ((size_t)(b_0 * NH + h) * DH + d) * SS + s_0;
                    float* base1 = ga.out + ((size_t)(b_1 * NH + h) * DH + d) * SS + s_1;
                    base0[0] = v00; base0[SS] = v01;
                    base1[0] = v10; base1[SS] = v11;
                }
            }
        }
    }
#undef G_LOAD
#undef G_STORE
}

// ---------------------------------------------------------------------------
// TF32 flash attention. 256 threads = 8 warps x 16q, cp.async double-buffered
// raw K/V + in-place tf32 convert pass. Conflict-free stride-68 layouts.
// 2 CTAs/SM (smem 102 KB x 2 = 204 KB) -> 16 warps/SM.
// ---------------------------------------------------------------------------
#define KS0 8704
#define VS0 17408
#define ATT_SMEM_U32 (8704 + 2*4352 + 2*4352)   // 26112 u32 = 102 KB

__global__ __launch_bounds__(256, 2) void attn_tf32(const float* __restrict__ mask,
                                                    float* __restrict__ outp)
{
    extern __shared__ __align__(16) unsigned smu[];
    unsigned* Ps = smu;              // Q stage (tf32), then per-warp P buffer

    const int tid  = threadIdx.x;
    const int lane = tid & 31, wid = tid >> 5;
    const int g = lane >> 2, t = lane & 3;
    const int q0 = blockIdx.x * 128;
    const int h  = blockIdx.y;
    const int b  = blockIdx.z;
    const float* Qg  = g_qh + (size_t)(b * NH + h) * SS * DH;
    const float* Kg  = g_kh + (size_t)(b * NH + h) * SS * DH;
    const float* Vtg = g_vt + (size_t)(b * NH + h) * DH * SS;

    const unsigned smb = (unsigned)__cvta_generic_to_shared(smu);
    const int s_cq = (tid & 15) << 2, s_rr = tid >> 4;   // 16 col-quads x 16 rows

    float o[8][4];
    #pragma unroll
    for (int j = 0; j < 8; j++)
        #pragma unroll
        for (int r = 0; r < 4; r++) o[j][r] = 0.f;
    float mrow[2] = {-1e30f, -1e30f};
    float lrow[2] = {0.f, 0.f};

#define ISSUE_TILE(K0, BUF) do {                                            \
    const unsigned kb = smb + (KS0 + (BUF) * 4352u) * 4;                    \
    const unsigned vb = smb + (VS0 + (BUF) * 4352u) * 4;                    \
    _Pragma("unroll")                                                       \
    for (int i = 0; i < 4; i++) {                                           \
        int row = s_rr + i * 16;                                            \
        CP_A16(kb + (row * 68 + s_cq) * 4,                                  \
               Kg + (size_t)((K0) + row) * DH + s_cq);                      \
        CP_A16(vb + (row * 68 + s_cq) * 4,                                  \
               Vtg + (size_t)row * SS + (K0) + s_cq);                       \
    }                                                                       \
    CP_COMMIT();                                                            \
} while (0)

    // Kick off tile 0 before Q staging (overlaps with Q LDGs)
    ISSUE_TILE(0, 0);

    // Stage Q tile (128 x 64) row-major stride 68 (tf32, producer-side cvt)
    #pragma unroll
    for (int i = 0; i < 8; i++) {
        int q = s_rr + i * 16;
        float4 v = *(const float4*)(Qg + (size_t)(q0 + q) * DH + s_cq);
        *(uint4*)&Ps[q * 68 + s_cq] = cvt4(v);
    }
    __syncthreads();

    // Hoist warp's Q fragments (warp owns 16 q rows)
    unsigned qa[8][4];
    {
        const unsigned qB = (wid * 16 + g) * 68 + t;
        #pragma unroll
        for (int ktd = 0; ktd < 8; ktd++) {
            unsigned base = qB + ktd * 8;
            qa[ktd][0] = Ps[base];
            qa[ktd][1] = Ps[base + 544];
            qa[ktd][2] = Ps[base + 4];
            qa[ktd][3] = Ps[base + 548];
        }
    }

    const unsigned pW = wid * 1088;           // per-warp P base (16 rows x 68)
    const unsigned kB = g * 68 + t;

    for (int it = 0; it < SS / 64; it++) {
        const int buf = it & 1, k0 = it * 64;

        // Top barrier: all warps done computing tile it-1.
        __syncthreads();
        if (it + 1 < SS / 64) {
            ISSUE_TILE((it + 1) * 64, (it + 1) & 1);
            CP_WAIT1();
        } else {
            CP_WAIT0();
        }
        __syncthreads();   // tile it's raw data visible

        // In-place convert pass: raw f32 -> tf32
        {
            unsigned* kbuf = smu + KS0 + buf * 4352;
            unsigned* vbuf = smu + VS0 + buf * 4352;
            #pragma unroll
            for (int i = 0; i < 4; i++) {
                int row = s_rr + i * 16;
                float4 kv = *(const float4*)&kbuf[row * 68 + s_cq];
                *(uint4*)&kbuf[row * 68 + s_cq] = cvt4(kv);
                float4 vv = *(const float4*)&vbuf[row * 68 + s_cq];
                *(uint4*)&vbuf[row * 68 + s_cq] = cvt4(vv);
            }
        }
        __syncthreads();   // converted tile visible

        const unsigned* Ksb  = smu + KS0 + buf * 4352;
        const unsigned* Vtsb = smu + VS0 + buf * 4352;

        // Scores: 16q x 64k per warp
        float s[8][4];
        #pragma unroll
        for (int j = 0; j < 8; j++)
            #pragma unroll
            for (int r = 0; r < 4; r++) s[j][r] = 0.f;

        #pragma unroll
        for (int ktd = 0; ktd < 8; ktd++) {
            #pragma unroll
            for (int nt = 0; nt < 8; nt++) {
                unsigned bk[2];
                unsigned base = kB + nt * 544 + ktd * 8;
                bk[0] = Ksb[base];
                bk[1] = Ksb[base + 4];
                mma_tf32(s[nt], qa[ktd], bk);
            }
        }

        // Scale + mask
        {
            int r0 = q0 + wid * 16 + g;
            int r1 = r0 + 8;
            #pragma unroll
            for (int nt = 0; nt < 8; nt++) {
                int col = k0 + nt * 8 + t * 2;
                float2 mk0 = __ldg((const float2*)(mask + (size_t)r0 * SS + col));
                float2 mk1 = __ldg((const float2*)(mask + (size_t)r1 * SS + col));
                s[nt][0] = s[nt][0] * 0.125f - 1e9f * mk0.x;
                s[nt][1] = s[nt][1] * 0.125f - 1e9f * mk0.y;
                s[nt][2] = s[nt][2] * 0.125f - 1e9f * mk1.x;
                s[nt][3] = s[nt][3] * 0.125f - 1e9f * mk1.y;
            }
        }

        // Online softmax (rows g, g+8; stats shared within lane quad)
        {
            float mx0 = -1e30f, mx1 = -1e30f;
            #pragma unroll
            for (int nt = 0; nt < 8; nt++) {
                mx0 = fmaxf(mx0, fmaxf(s[nt][0], s[nt][1]));
                mx1 = fmaxf(mx1, fmaxf(s[nt][2], s[nt][3]));
            }
            mx0 = fmaxf(mx0, __shfl_xor_sync(0xffffffffu, mx0, 1));
            mx0 = fmaxf(mx0, __shfl_xor_sync(0xffffffffu, mx0, 2));
            mx1 = fmaxf(mx1, __shfl_xor_sync(0xffffffffu, mx1, 1));
            mx1 = fmaxf(mx1, __shfl_xor_sync(0xffffffffu, mx1, 2));

            float nm0 = fmaxf(mrow[0], mx0), nm1 = fmaxf(mrow[1], mx1);
            float al0 = __expf(mrow[0] - nm0), al1 = __expf(mrow[1] - nm1);
            float sum0 = 0.f, sum1 = 0.f;
            #pragma unroll
            for (int nt = 0; nt < 8; nt++) {
                float p0 = __expf(s[nt][0] - nm0);
                float p1 = __expf(s[nt][1] - nm0);
                float p2 = __expf(s[nt][2] - nm1);
                float p3 = __expf(s[nt][3] - nm1);
                s[nt][0] = p0; s[nt][1] = p1;
                s[nt][2] = p2; s[nt][3] = p3;
                sum0 += p0 + p1;
                sum1 += p2 + p3;
            }
            sum0 += __shfl_xor_sync(0xffffffffu, sum0, 1);
            sum0 += __shfl_xor_sync(0xffffffffu, sum0, 2);
            sum1 += __shfl_xor_sync(0xffffffffu, sum1, 1);
            sum1 += __shfl_xor_sync(0xffffffffu, sum1, 2);
            lrow[0] = lrow[0] * al0 + sum0;
            lrow[1] = lrow[1] * al1 + sum1;
            mrow[0] = nm0; mrow[1] = nm1;

            #pragma unroll
            for (int nt = 0; nt < 8; nt++) {
                o[nt][0] *= al0; o[nt][1] *= al0;
                o[nt][2] *= al1; o[nt][3] *= al1;
            }
        }

        // Store P (tf32) into warp's own band
        #pragma unroll
        for (int nt = 0; nt < 8; nt++) {
            unsigned idx = pW + g * 68 + nt * 8 + t * 2;
            uint2 p01 = make_uint2(tf32r(s[nt][0]), tf32r(s[nt][1]));
            *(uint2*)&Ps[idx] = p01;
            uint2 p23 = make_uint2(tf32r(s[nt][2]), tf32r(s[nt][3]));
            *(uint2*)&Ps[idx + 544] = p23;
        }
        __syncwarp();

        // PV: A-frag of P, B = V^T tiles
        const unsigned pA = pW + g * 68 + t;
        #pragma unroll
        for (int ktk = 0; ktk < 8; ktk++) {
            unsigned ap[4];
            unsigned base = pA + ktk * 8;
            ap[0] = Ps[base];
            ap[1] = Ps[base + 544];
            ap[2] = Ps[base + 4];
            ap[3] = Ps[base + 548];
            #pragma unroll
            for (int ntd = 0; ntd < 8; ntd++) {
                unsigned bv[2];
                unsigned vb = kB + ntd * 544 + ktk * 8;
                bv[0] = Vtsb[vb];
                bv[1] = Vtsb[vb + 4];
                mma_tf32(o[ntd], ap, bv);
            }
        }
    }

    // Epilogue: normalize + write merged-head layout
    {
        float inv0 = 1.0f / lrow[0], inv1 = 1.0f / lrow[1];
        int r0 = q0 + wid * 16 + g;
        int r1 = r0 + 8;
        #pragma unroll
        for (int ntd = 0; ntd < 8; ntd++) {
            int col = h * DH + ntd * 8 + t * 2;
            float2 v0 = make_float2(o[ntd][0] * inv0, o[ntd][1] * inv0);
            float2 v1 = make_float2(o[ntd][2] * inv1, o[ntd][3] * inv1);
            *(float2*)(outp + ((size_t)b * SS + r0) * DM + col) = v0;
            *(float2*)(outp + ((size_t)b * SS + r1) * DM + col) = v1;
        }
    }
#undef ISSUE_TILE
}

// ---------------------------------------------------------------------------
extern "C" void kernel_launch(void* const* d_in, const int* in_sizes, int n_in,
                              void* d_out, int out_size)
{
    const float* q    = (const float*)d_in[0];
    const float* k    = (const float*)d_in[1];
    const float* v    = (const float*)d_in[2];
    const float* mask = (const float*)d_in[3];
    const float* wq   = (const float*)d_in[4];
    const float* bq   = (const float*)d_in[5];
    const float* wk   = (const float*)d_in[6];
    const float* bk   = (const float*)d_in[7];
    const float* wv   = (const float*)d_in[8];
    const float* bv   = (const float*)d_in[9];
    const float* wo   = (const float*)d_in[10];
    const float* bo   = (const float*)d_in[11];

    float *qh, *kh, *vt, *at, *wT;
    cudaGetSymbolAddress((void**)&qh, g_qh);
    cudaGetSymbolAddress((void**)&kh, g_kh);
    cudaGetSymbolAddress((void**)&vt, g_vt);
    cudaGetSymbolAddress((void**)&at, g_at);
    cudaGetSymbolAddress((void**)&wT, g_wT);

    const int attn_smem = ATT_SMEM_U32 * (int)sizeof(unsigned);   // ~102 KB
    cudaFuncSetAttribute(attn_tf32, cudaFuncAttributeMaxDynamicSharedMemorySize,
                         attn_smem);

    // Fused weight transposes (one launch)
    dim3 tb(32, 8), tg(32, 32, 4);
    transp4<<<tg, tb>>>(wq, wk, wv, wo, wT);

    // Fused Q/K/V projections (V written transposed)
    G3 pqkv;
    pqkv.g[0] = GA{q, wT + 0 * DM * DM, bq, qh, 1};
    pqkv.g[1] = GA{k, wT + 1 * DM * DM, bk, kh, 1};
    pqkv.g[2] = GA{v, wT + 2 * DM * DM, bv, vt, 2};
    dim3 gqkv(DM / 128, MT / 128, 3);
    gemm_tf32<<<gqkv, 256>>>(pqkv);

    dim3 ga(SS / 128, NH, BB);
    attn_tf32<<<ga, 256, attn_smem>>>(mask, at);

    G3 po;
    po.g[0] = GA{at, wT + 3 * DM * DM, bo, (float*)d_out, 0};
    po.g[1] = po.g[0];
    po.g[2] = po.g[0];
    dim3 go(DM / 128, MT / 128, 1);
    gemm_tf32<<<go, 256>>>(po);
}